// round 5
// baseline (speedup 1.0000x reference)
#include <cuda_runtime.h>

// Scratch for the extracted diagonal (allocation-free: __device__ global).
__device__ float g_diag[4096];

// Kernel A: pull diag(W) out of the dense [4096,4096] matrix.
__global__ void extract_diag_kernel(const float* __restrict__ W) {
    int j = blockIdx.x * blockDim.x + threadIdx.x;
    if (j < 4096) {
        g_diag[j] = __ldg(&W[(size_t)j * 4097u]);
    }
}

// Kernel B: y = x * diag (columnwise), 4 linear streams, ILP=4.
// Total 8,388,608 float4; Q = total/4 = 2,097,152 (multiple of 1024,
// so all four elements of a thread share the same column/diag value).
#define Q 2097152u

__global__ void diag_scale_kernel(const float4* __restrict__ x,
                                  float4* __restrict__ y) {
    const unsigned int i = blockIdx.x * blockDim.x + threadIdx.x;  // < Q
    const float4* d4 = reinterpret_cast<const float4*>(g_diag);

    const float4 d = __ldg(&d4[i & 1023u]);   // 16KB, L1/L2-hot

    // 4 independent streaming loads -> max per-thread MLP.
    float4 a = __ldcs(&x[i]);
    float4 b = __ldcs(&x[i + Q]);
    float4 c = __ldcs(&x[i + 2u * Q]);
    float4 e = __ldcs(&x[i + 3u * Q]);

    a.x *= d.x; a.y *= d.y; a.z *= d.z; a.w *= d.w;
    b.x *= d.x; b.y *= d.y; b.z *= d.z; b.w *= d.w;
    c.x *= d.x; c.y *= d.y; c.z *= d.z; c.w *= d.w;
    e.x *= d.x; e.y *= d.y; e.z *= d.z; e.w *= d.w;

    __stcs(&y[i], a);
    __stcs(&y[i + Q], b);
    __stcs(&y[i + 2u * Q], c);
    __stcs(&y[i + 3u * Q], e);
}

extern "C" void kernel_launch(void* const* d_in, const int* in_sizes, int n_in,
                              void* d_out, int out_size) {
    const float* x = (const float*)d_in[0];
    const float* W = (const float*)d_in[1];
    float* y = (float*)d_out;

    extract_diag_kernel<<<16, 256>>>(W);

    // Q threads, each doing 4 float4: 2,097,152 / 256 = 8192 blocks.
    diag_scale_kernel<<<8192, 256>>>((const float4*)x, (float4*)y);
}